// round 1
// baseline (speedup 1.0000x reference)
#include <cuda_runtime.h>
#include <cstdint>

// ---------------------------------------------------------------------------
// GAT layer, algebraically reduced.
//
// reference:  h_new[n,h] = h_proj[n,h] * sum_{e: src[e]=n} alpha[e,h]
//             sum alpha = denom/(denom+1e-16)  ==  1{outdeg(n)>0}  in fp32
// so:         out = (h_in @ W.T + b) * outdeg_mask
// ---------------------------------------------------------------------------

#define MASK_CAP (1 << 24)
__device__ unsigned char g_mask[MASK_CAP];

__global__ void zero_mask_kernel(int n_words) {
    int i = blockIdx.x * blockDim.x + threadIdx.x;
    if (i < n_words) reinterpret_cast<unsigned int*>(g_mask)[i] = 0u;
}

__global__ void scatter_mask_kernel(const int* __restrict__ src, int E4, int E) {
    int i = blockIdx.x * blockDim.x + threadIdx.x;
    if (i < E4) {
        int4 s = reinterpret_cast<const int4*>(src)[i];
        g_mask[s.x] = 1; g_mask[s.y] = 1; g_mask[s.z] = 1; g_mask[s.w] = 1;
    }
    // tail (E not divisible by 4)
    int t = E4 * 4 + i;
    if (i < (E - E4 * 4)) {
        // note: only valid when tail exists; guarded above
    }
    if (i == 0) {
        for (int j = E4 * 4; j < E; ++j) g_mask[src[j]] = 1;
    }
}

// ---------------------------------------------------------------------------
// Fast path: F_IN=128, HF=32. 2 rows/thread, packed fp32 (fma.rn.f32x2).
// ---------------------------------------------------------------------------
__device__ __forceinline__ unsigned long long pack2(float x, float y) {
    unsigned long long r;
    asm("mov.b64 %0, {%1, %2};" : "=l"(r) : "f"(x), "f"(y));
    return r;
}
__device__ __forceinline__ float2 unpack2(unsigned long long v) {
    float2 r;
    asm("mov.b64 {%0, %1}, %2;" : "=f"(r.x), "=f"(r.y) : "l"(v));
    return r;
}
__device__ __forceinline__ void fma2(unsigned long long& acc,
                                     unsigned long long a, unsigned long long b) {
    asm("fma.rn.f32x2 %0, %1, %2, %3;" : "=l"(acc) : "l"(a), "l"(b), "l"(acc));
}

__global__ __launch_bounds__(256) void gat_gemm_mask_kernel(
    const float* __restrict__ h_in,   // [n, 128]
    const float* __restrict__ W,      // [32, 128] row-major
    const float* __restrict__ b,      // [32]
    float* __restrict__ out,          // [n, 32]
    int n)
{
    constexpr int F_IN = 128;
    constexpr int HF   = 32;

    __shared__ __align__(16) unsigned long long Ws2[F_IN * (HF / 2)];  // [k][j2], 16KB
    __shared__ float bs[HF];

    int tid = threadIdx.x;
    // transpose W into pair-interleaved shared layout: Ws2[k*16 + j2] = (W[2j2][k], W[2j2+1][k])
    {
        float* Wsf = reinterpret_cast<float*>(Ws2);
        for (int idx = tid; idx < F_IN * HF; idx += 256) {
            int k = idx / HF, j = idx % HF;
            Wsf[k * HF + j] = W[j * F_IN + k];
        }
        if (tid < HF) bs[tid] = b[tid];
    }
    __syncthreads();

    long long base = (long long)blockIdx.x * 512;
    int rA = (int)(base + tid);
    int rB = (int)(base + 256 + tid);
    bool vA = rA < n, vB = rB < n;

    unsigned long long accA[16], accB[16];
    #pragma unroll
    for (int j2 = 0; j2 < 16; ++j2) {
        unsigned long long bb = pack2(bs[2 * j2], bs[2 * j2 + 1]);
        accA[j2] = bb;
        accB[j2] = bb;
    }

    const float4* __restrict__ hA4 =
        reinterpret_cast<const float4*>(h_in + (size_t)(vA ? rA : 0) * F_IN);
    const float4* __restrict__ hB4 =
        reinterpret_cast<const float4*>(h_in + (size_t)(vB ? rB : 0) * F_IN);

    #pragma unroll 2
    for (int k4 = 0; k4 < F_IN / 4; ++k4) {
        float4 a4 = hA4[k4];
        float4 c4 = hB4[k4];
        float ax[4] = {a4.x, a4.y, a4.z, a4.w};
        float cx[4] = {c4.x, c4.y, c4.z, c4.w};
        #pragma unroll
        for (int u = 0; u < 4; ++u) {
            int k = k4 * 4 + u;
            unsigned long long xa = pack2(ax[u], ax[u]);
            unsigned long long xb = pack2(cx[u], cx[u]);
            const ulonglong2* wrow = reinterpret_cast<const ulonglong2*>(Ws2 + k * 16);
            #pragma unroll
            for (int j4 = 0; j4 < 8; ++j4) {
                ulonglong2 w = wrow[j4];   // LDS.128, warp-broadcast (conflict-free)
                fma2(accA[2 * j4 + 0], xa, w.x);
                fma2(accA[2 * j4 + 1], xa, w.y);
                fma2(accB[2 * j4 + 0], xb, w.x);
                fma2(accB[2 * j4 + 1], xb, w.y);
            }
        }
    }

    if (vA) {
        float m = g_mask[rA] ? 1.0f : 0.0f;
        float2* o = reinterpret_cast<float2*>(out + (size_t)rA * HF);
        #pragma unroll
        for (int j2 = 0; j2 < 16; ++j2) {
            float2 v = unpack2(accA[j2]);
            v.x *= m; v.y *= m;
            o[j2] = v;
        }
    }
    if (vB) {
        float m = g_mask[rB] ? 1.0f : 0.0f;
        float2* o = reinterpret_cast<float2*>(out + (size_t)rB * HF);
        #pragma unroll
        for (int j2 = 0; j2 < 16; ++j2) {
            float2 v = unpack2(accB[j2]);
            v.x *= m; v.y *= m;
            o[j2] = v;
        }
    }
}

// ---------------------------------------------------------------------------
// Generic fallback (any dims) — correctness insurance only.
// ---------------------------------------------------------------------------
__global__ void gat_generic_kernel(
    const float* __restrict__ h_in, const float* __restrict__ W,
    const float* __restrict__ b, float* __restrict__ out,
    int n, int f_in, int hf)
{
    long long idx = (long long)blockIdx.x * blockDim.x + threadIdx.x;
    if (idx >= (long long)n * hf) return;
    int node = (int)(idx / hf);
    int j    = (int)(idx % hf);
    const float* hr = h_in + (size_t)node * f_in;
    const float* wr = W + (size_t)j * f_in;
    float acc = b[j];
    for (int k = 0; k < f_in; ++k) acc += hr[k] * wr[k];
    out[idx] = g_mask[node] ? acc : 0.0f;
}

extern "C" void kernel_launch(void* const* d_in, const int* in_sizes, int n_in,
                              void* d_out, int out_size) {
    const float* h_in = (const float*)d_in[0];
    const float* W    = (const float*)d_in[1];
    const float* b    = (const float*)d_in[2];
    // d_in[3] = a_src, d_in[4] = a_tgt : provably unused after reduction
    const int* edge_index = (const int*)d_in[5];

    int HF   = in_sizes[2];               // H * F_OUT
    int F_IN = in_sizes[1] / HF;
    int n    = in_sizes[0] / F_IN;
    int E    = in_sizes[5] / 2;
    const int* src = edge_index;          // row 0 of [2, E]

    float* out = (float*)d_out;

    // 1) zero the out-degree mask (word stores; mask region = n bytes)
    int n_words = (n + 3) / 4;
    zero_mask_kernel<<<(n_words + 255) / 256, 256>>>(n_words);

    // 2) scatter mask from src column
    int E4 = E / 4;
    scatter_mask_kernel<<<(E4 + 255) / 256, 256>>>(src, E4, E);

    // 3) fused GEMM + bias + mask
    if (F_IN == 128 && HF == 32) {
        int blocks = (n + 511) / 512;
        gat_gemm_mask_kernel<<<blocks, 256>>>(h_in, W, b, out, n);
    } else {
        long long total = (long long)n * HF;
        int blocks = (int)((total + 255) / 256);
        gat_generic_kernel<<<blocks, 256>>>(h_in, W, b, out, n, F_IN, HF);
    }
    (void)n_in; (void)out_size;
}

// round 2
// speedup vs baseline: 1.0742x; 1.0742x over previous
#include <cuda_runtime.h>
#include <cstdint>

// ---------------------------------------------------------------------------
// GAT layer, algebraically reduced:
//   Sum_{e: src=n} alpha[e,h] = denom/(denom+1e-16) == 1{outdeg(n)>0} in fp32
//   => out = (h_in @ W.T + b) * outdeg_mask
//
// Structure (2 launches):
//   K1 (fused): scatter CTAs set g_mask[src]=1  ||  gemm CTAs write unmasked out
//   K2 (maskfix): rows with mask==0 -> zeroed; mask byte reset to 0 (self-clean
//                 for next graph replay; __device__ global starts zeroed).
// ---------------------------------------------------------------------------

#define MASK_CAP (1 << 20)
__device__ unsigned char g_mask[MASK_CAP];

__device__ __forceinline__ unsigned long long pack2(float x, float y) {
    unsigned long long r;
    asm("mov.b64 %0, {%1, %2};" : "=l"(r) : "f"(x), "f"(y));
    return r;
}
__device__ __forceinline__ float2 unpack2(unsigned long long v) {
    float2 r;
    asm("mov.b64 {%0, %1}, %2;" : "=f"(r.x), "=f"(r.y) : "l"(v));
    return r;
}
__device__ __forceinline__ void fma2(unsigned long long& acc,
                                     unsigned long long a, unsigned long long b) {
    asm("fma.rn.f32x2 %0, %1, %2, %3;" : "=l"(acc) : "l"(a), "l"(b), "l"(acc));
}

// ---------------------------------------------------------------------------
// K1: fused scatter + GEMM. Blocks [0, scatterBlocks) scatter the mask;
// blocks [scatterBlocks, scatterBlocks+gemmBlocks) do the 128->32 GEMM.
// Scatter blocks come first so the long-pole work starts immediately.
// ---------------------------------------------------------------------------
__global__ __launch_bounds__(256) void fused_scatter_gemm_kernel(
    const float* __restrict__ h_in,   // [n, 128]
    const float* __restrict__ W,      // [32, 128] row-major
    const float* __restrict__ b,      // [32]
    float* __restrict__ out,          // [n, 32]
    int n,
    const int* __restrict__ src,      // [E]
    int E,
    int scatterBlocks)
{
    constexpr int F_IN = 128;
    constexpr int HF   = 32;

    if ((int)blockIdx.x < scatterBlocks) {
        // ---------------- scatter role ----------------
        int t      = blockIdx.x * 256 + threadIdx.x;
        int stride = scatterBlocks * 256;
        int E4     = E >> 2;
        const int4* __restrict__ s4 = reinterpret_cast<const int4*>(src);
        for (int i = t; i < E4; i += stride) {
            int4 s = s4[i];
            g_mask[s.x] = 1; g_mask[s.y] = 1; g_mask[s.z] = 1; g_mask[s.w] = 1;
        }
        for (int i = E4 * 4 + t; i < E; i += stride) g_mask[src[i]] = 1;
        return;
    }

    // ---------------- gemm role ----------------
    __shared__ __align__(16) unsigned long long Ws2[F_IN * (HF / 2)];  // 16KB
    __shared__ float bs[HF];

    int tid = threadIdx.x;
    {
        float* Wsf = reinterpret_cast<float*>(Ws2);
        for (int idx = tid; idx < F_IN * HF; idx += 256) {
            int k = idx / HF, j = idx % HF;
            Wsf[k * HF + j] = W[j * F_IN + k];
        }
        if (tid < HF) bs[tid] = b[tid];
    }
    __syncthreads();

    long long base = (long long)(blockIdx.x - scatterBlocks) * 512;
    int rA = (int)(base + tid);
    int rB = (int)(base + 256 + tid);
    bool vA = rA < n, vB = rB < n;

    unsigned long long accA[16], accB[16];
    #pragma unroll
    for (int j2 = 0; j2 < 16; ++j2) {
        unsigned long long bb = pack2(bs[2 * j2], bs[2 * j2 + 1]);
        accA[j2] = bb;
        accB[j2] = bb;
    }

    const float4* __restrict__ hA4 =
        reinterpret_cast<const float4*>(h_in + (size_t)(vA ? rA : 0) * F_IN);
    const float4* __restrict__ hB4 =
        reinterpret_cast<const float4*>(h_in + (size_t)(vB ? rB : 0) * F_IN);

    #pragma unroll 2
    for (int k4 = 0; k4 < F_IN / 4; ++k4) {
        float4 a4 = hA4[k4];
        float4 c4 = hB4[k4];
        float ax[4] = {a4.x, a4.y, a4.z, a4.w};
        float cx[4] = {c4.x, c4.y, c4.z, c4.w};
        #pragma unroll
        for (int u = 0; u < 4; ++u) {
            int k = k4 * 4 + u;
            unsigned long long xa = pack2(ax[u], ax[u]);
            unsigned long long xb = pack2(cx[u], cx[u]);
            const ulonglong2* wrow = reinterpret_cast<const ulonglong2*>(Ws2 + k * 16);
            #pragma unroll
            for (int j4 = 0; j4 < 8; ++j4) {
                ulonglong2 w = wrow[j4];   // LDS.128 broadcast, conflict-free
                fma2(accA[2 * j4 + 0], xa, w.x);
                fma2(accA[2 * j4 + 1], xa, w.y);
                fma2(accB[2 * j4 + 0], xb, w.x);
                fma2(accB[2 * j4 + 1], xb, w.y);
            }
        }
    }

    if (vA) {
        float4* o = reinterpret_cast<float4*>(out + (size_t)rA * HF);
        #pragma unroll
        for (int j4 = 0; j4 < 8; ++j4) {
            float2 v0 = unpack2(accA[2 * j4 + 0]);
            float2 v1 = unpack2(accA[2 * j4 + 1]);
            o[j4] = make_float4(v0.x, v0.y, v1.x, v1.y);   // STG.128
        }
    }
    if (vB) {
        float4* o = reinterpret_cast<float4*>(out + (size_t)rB * HF);
        #pragma unroll
        for (int j4 = 0; j4 < 8; ++j4) {
            float2 v0 = unpack2(accB[2 * j4 + 0]);
            float2 v1 = unpack2(accB[2 * j4 + 1]);
            o[j4] = make_float4(v0.x, v0.y, v1.x, v1.y);
        }
    }
}

// ---------------------------------------------------------------------------
// K2: zero rows of absent nodes, and reset the mask byte for the next replay.
// ---------------------------------------------------------------------------
__global__ __launch_bounds__(256) void maskfix_kernel(
    float* __restrict__ out, int n, int hf)
{
    int i = blockIdx.x * 256 + threadIdx.x;
    if (i >= n) return;
    unsigned char m = g_mask[i];
    g_mask[i] = 0;                       // self-clean for next call
    if (!m) {
        float* o = out + (size_t)i * hf;
        for (int j = 0; j < hf; ++j) o[j] = 0.0f;  // rare (E/N=16 random)
    }
}

// ---------------------------------------------------------------------------
// Generic fallbacks (any dims) — correctness insurance only.
// ---------------------------------------------------------------------------
__global__ void generic_scatter_kernel(const int* __restrict__ src, int E) {
    int i = blockIdx.x * blockDim.x + threadIdx.x;
    int stride = gridDim.x * blockDim.x;
    for (int e = i; e < E; e += stride) g_mask[src[e]] = 1;
}

__global__ void generic_gemm_kernel(
    const float* __restrict__ h_in, const float* __restrict__ W,
    const float* __restrict__ b, float* __restrict__ out,
    int n, int f_in, int hf)
{
    long long idx = (long long)blockIdx.x * blockDim.x + threadIdx.x;
    if (idx >= (long long)n * hf) return;
    int node = (int)(idx / hf);
    int j    = (int)(idx % hf);
    const float* hr = h_in + (size_t)node * f_in;
    const float* wr = W + (size_t)j * f_in;
    float acc = b[j];
    for (int k = 0; k < f_in; ++k) acc += hr[k] * wr[k];
    out[idx] = acc;
}

extern "C" void kernel_launch(void* const* d_in, const int* in_sizes, int n_in,
                              void* d_out, int out_size) {
    const float* h_in = (const float*)d_in[0];
    const float* W    = (const float*)d_in[1];
    const float* b    = (const float*)d_in[2];
    // d_in[3]=a_src, d_in[4]=a_tgt: provably unused after reduction
    const int* edge_index = (const int*)d_in[5];

    int HF   = in_sizes[2];               // H * F_OUT
    int F_IN = in_sizes[1] / HF;
    int n    = in_sizes[0] / F_IN;
    int E    = in_sizes[5] / 2;
    const int* src = edge_index;          // row 0 of [2, E]

    float* out = (float*)d_out;

    if (F_IN == 128 && HF == 32 && n <= MASK_CAP) {
        int gemmBlocks    = (n + 511) / 512;
        int scatterBlocks = 512;
        fused_scatter_gemm_kernel<<<scatterBlocks + gemmBlocks, 256>>>(
            h_in, W, b, out, n, src, E, scatterBlocks);
        maskfix_kernel<<<(n + 255) / 256, 256>>>(out, n, HF);
    } else {
        generic_scatter_kernel<<<1024, 256>>>(src, E);
        long long total = (long long)n * HF;
        generic_gemm_kernel<<<(int)((total + 255) / 256), 256>>>(
            h_in, W, b, out, n, F_IN, HF);
        maskfix_kernel<<<(n + 255) / 256, 256>>>(out, n, HF);
    }
    (void)n_in; (void)out_size;
}

// round 3
// speedup vs baseline: 1.1108x; 1.0341x over previous
#include <cuda_runtime.h>
#include <cstdint>

// ---------------------------------------------------------------------------
// GAT layer, algebraically reduced:
//   Sum_{e: src=n} alpha[e,h] == 1{outdeg(n)>0} in fp32
//   => out = (h_in @ W.T + b) * outdeg_mask
//
// R2 lesson: 6.4M random byte stores into a 100KB global mask serialize on
// ~4 L2 lines per LTS (~65us). Fix: per-CTA private byte-map in SMEM (plain
// STS), bit-pack, merge via atomicOr words (925K ops on distinct words).
// ---------------------------------------------------------------------------

#define MASK_CAP (1 << 20)
__device__ unsigned char g_mask[MASK_CAP];        // generic fallback path
__device__ unsigned int  g_bits[MASK_CAP / 32];   // fast path (bit per node)

__device__ __forceinline__ unsigned long long pack2(float x, float y) {
    unsigned long long r;
    asm("mov.b64 %0, {%1, %2};" : "=l"(r) : "f"(x), "f"(y));
    return r;
}
__device__ __forceinline__ float2 unpack2(unsigned long long v) {
    float2 r;
    asm("mov.b64 {%0, %1}, %2;" : "=f"(r.x), "=f"(r.y) : "l"(v));
    return r;
}
__device__ __forceinline__ void fma2(unsigned long long& acc,
                                     unsigned long long a, unsigned long long b) {
    asm("fma.rn.f32x2 %0, %1, %2, %3;" : "=l"(acc) : "l"(a), "l"(b), "l"(acc));
}
// bytes (0/1) of v -> 4 bits, byte j -> bit j
__device__ __forceinline__ unsigned nib(unsigned v) {
    return (((v & 0x01010101u) * 0x01020408u) >> 24) & 0xFu;
}

// ---------------------------------------------------------------------------
// Fused kernel: every CTA does (scatter chunk -> merge) then (gemm chunk).
// Dynamic smem: phase A = byte map [mapBytes]; phase B (reuse) = W pairs 16KB
// + bias 128B.
// ---------------------------------------------------------------------------
__global__ __launch_bounds__(256) void fused_kernel(
    const float* __restrict__ h_in,   // [n, 128]
    const float* __restrict__ W,      // [32, 128]
    const float* __restrict__ b,      // [32]
    float* __restrict__ out,          // [n, 32]
    int n,
    const int* __restrict__ src,      // [E]
    int E,
    int mapBytes)
{
    constexpr int F_IN = 128;
    constexpr int HF   = 32;
    extern __shared__ __align__(16) char dsm[];
    const int tid = threadIdx.x;
    const int g   = gridDim.x;

    // ---- phase A1: zero private byte map ----
    {
        int4* m4 = reinterpret_cast<int4*>(dsm);
        const int nm4 = mapBytes >> 4;
        for (int i = tid; i < nm4; i += 256) m4[i] = make_int4(0, 0, 0, 0);
    }
    __syncthreads();

    // ---- phase A2: scatter this CTA's contiguous edge chunk (plain STS) ----
    {
        const int E4  = E >> 2;
        const int per = (E4 + g - 1) / g;
        const int s4  = blockIdx.x * per;
        const int e4  = min(s4 + per, E4);
        const int4* __restrict__ sp = reinterpret_cast<const int4*>(src);
        for (int i = s4 + tid; i < e4; i += 256) {
            int4 s = sp[i];
            if ((unsigned)s.x < (unsigned)n) dsm[s.x] = 1;
            if ((unsigned)s.y < (unsigned)n) dsm[s.y] = 1;
            if ((unsigned)s.z < (unsigned)n) dsm[s.z] = 1;
            if ((unsigned)s.w < (unsigned)n) dsm[s.w] = 1;
        }
        if (blockIdx.x == g - 1) {                  // scalar tail
            for (int i = (E4 << 2) + tid; i < E; i += 256) {
                int s = src[i];
                if ((unsigned)s < (unsigned)n) dsm[s] = 1;
            }
        }
    }
    __syncthreads();

    // ---- phase A3: bit-pack + merge into global bit mask ----
    {
        const int nWords = (n + 31) >> 5;
        const uint4* mv = reinterpret_cast<const uint4*>(dsm);
        for (int w = tid; w < nWords; w += 256) {
            uint4 a = mv[2 * w + 0];
            uint4 c = mv[2 * w + 1];
            unsigned bits =  nib(a.x)        | (nib(a.y) << 4)
                          | (nib(a.z) << 8)  | (nib(a.w) << 12)
                          | (nib(c.x) << 16) | (nib(c.y) << 20)
                          | (nib(c.z) << 24) | (nib(c.w) << 28);
            if (bits) atomicOr(&g_bits[w], bits);
        }
    }
    __syncthreads();

    // ---- phase B1: load W (pair-interleaved) + bias into reused smem ----
    unsigned long long* Ws2 = reinterpret_cast<unsigned long long*>(dsm);
    float* bs = reinterpret_cast<float*>(dsm + 16384);
    {
        float* Wsf = reinterpret_cast<float*>(dsm);
        for (int idx = tid; idx < F_IN * HF; idx += 256) {
            int k = idx / HF, j = idx % HF;
            Wsf[k * HF + j] = W[j * F_IN + k];
        }
        if (tid < HF) bs[tid] = b[tid];
    }
    __syncthreads();

    // ---- phase B2: gemm, balanced contiguous pair-chunks per CTA ----
    const int pairs   = n >> 1;
    const int perPair = (pairs + g - 1) / g;
    const int p0      = blockIdx.x * perPair;
    const int p1      = min(p0 + perPair, pairs);

    for (int p = p0 + tid; p < p1; p += 256) {
        const int rA = 2 * p;
        const int rB = 2 * p + 1;

        unsigned long long accA[16], accB[16];
        #pragma unroll
        for (int j2 = 0; j2 < 16; ++j2) {
            unsigned long long bb = pack2(bs[2 * j2], bs[2 * j2 + 1]);
            accA[j2] = bb;
            accB[j2] = bb;
        }

        const float4* __restrict__ hA4 =
            reinterpret_cast<const float4*>(h_in + (size_t)rA * F_IN);
        const float4* __restrict__ hB4 =
            reinterpret_cast<const float4*>(h_in + (size_t)rB * F_IN);

        #pragma unroll 2
        for (int k4 = 0; k4 < F_IN / 4; ++k4) {
            float4 a4 = hA4[k4];
            float4 c4 = hB4[k4];
            float ax[4] = {a4.x, a4.y, a4.z, a4.w};
            float cx[4] = {c4.x, c4.y, c4.z, c4.w};
            #pragma unroll
            for (int u = 0; u < 4; ++u) {
                int k = k4 * 4 + u;
                unsigned long long xa = pack2(ax[u], ax[u]);
                unsigned long long xb = pack2(cx[u], cx[u]);
                const ulonglong2* wrow =
                    reinterpret_cast<const ulonglong2*>(Ws2 + k * 16);
                #pragma unroll
                for (int j4 = 0; j4 < 8; ++j4) {
                    ulonglong2 w = wrow[j4];   // LDS.128 broadcast
                    fma2(accA[2 * j4 + 0], xa, w.x);
                    fma2(accA[2 * j4 + 1], xa, w.y);
                    fma2(accB[2 * j4 + 0], xb, w.x);
                    fma2(accB[2 * j4 + 1], xb, w.y);
                }
            }
        }

        float4* oA = reinterpret_cast<float4*>(out + (size_t)rA * HF);
        float4* oB = reinterpret_cast<float4*>(out + (size_t)rB * HF);
        #pragma unroll
        for (int j4 = 0; j4 < 8; ++j4) {
            float2 a0 = unpack2(accA[2 * j4 + 0]);
            float2 a1 = unpack2(accA[2 * j4 + 1]);
            oA[j4] = make_float4(a0.x, a0.y, a1.x, a1.y);
            float2 b0 = unpack2(accB[2 * j4 + 0]);
            float2 b1 = unpack2(accB[2 * j4 + 1]);
            oB[j4] = make_float4(b0.x, b0.y, b1.x, b1.y);
        }
    }

    // odd final row (n odd) — scalar, one thread
    if ((n & 1) && blockIdx.x == 0 && tid == 0) {
        int r = n - 1;
        const float* hr = h_in + (size_t)r * F_IN;
        for (int j = 0; j < HF; ++j) {
            float acc = bs[j];
            const float* wr = W + (size_t)j * F_IN;
            for (int k = 0; k < F_IN; ++k) acc += hr[k] * wr[k];
            out[(size_t)r * HF + j] = acc;
        }
    }
}

// ---------------------------------------------------------------------------
// maskfix (bit version): zero rows of absent nodes; reset mask word (lane 0).
// ---------------------------------------------------------------------------
__global__ __launch_bounds__(256) void maskfix_bits_kernel(
    float* __restrict__ out, int n, int hf)
{
    int base = (blockIdx.x * 256 + threadIdx.x) & ~31;   // warp-aligned node base
    int lane = threadIdx.x & 31;
    if (base >= n) return;
    int w = base >> 5;
    unsigned bits = 0;
    if (lane == 0) {
        bits = g_bits[w];
        g_bits[w] = 0;            // self-clean for next graph replay
    }
    bits = __shfl_sync(0xffffffffu, bits, 0);
    int node = base + lane;
    if (node < n && !((bits >> lane) & 1u)) {
        float4* o = reinterpret_cast<float4*>(out + (size_t)node * hf);
        int q = hf >> 2;
        for (int j = 0; j < q; ++j) o[j] = make_float4(0.f, 0.f, 0.f, 0.f);
        for (int j = q << 2; j < hf; ++j) out[(size_t)node * hf + j] = 0.f;
    }
}

// ---------------------------------------------------------------------------
// Generic fallbacks (any dims) — correctness insurance only.
// ---------------------------------------------------------------------------
__global__ void generic_scatter_kernel(const int* __restrict__ src, int E) {
    int i = blockIdx.x * blockDim.x + threadIdx.x;
    int stride = gridDim.x * blockDim.x;
    for (int e = i; e < E; e += stride) g_mask[src[e]] = 1;
}
__global__ void generic_gemm_kernel(
    const float* __restrict__ h_in, const float* __restrict__ W,
    const float* __restrict__ b, float* __restrict__ out,
    int n, int f_in, int hf)
{
    long long idx = (long long)blockIdx.x * blockDim.x + threadIdx.x;
    if (idx >= (long long)n * hf) return;
    int node = (int)(idx / hf);
    int j    = (int)(idx % hf);
    const float* hr = h_in + (size_t)node * f_in;
    const float* wr = W + (size_t)j * f_in;
    float acc = b[j];
    for (int k = 0; k < f_in; ++k) acc += hr[k] * wr[k];
    out[idx] = acc;
}
__global__ void generic_maskfix_kernel(float* __restrict__ out, int n, int hf) {
    int i = blockIdx.x * blockDim.x + threadIdx.x;
    if (i >= n) return;
    unsigned char m = g_mask[i];
    g_mask[i] = 0;
    if (!m) {
        float* o = out + (size_t)i * hf;
        for (int j = 0; j < hf; ++j) o[j] = 0.0f;
    }
}

extern "C" void kernel_launch(void* const* d_in, const int* in_sizes, int n_in,
                              void* d_out, int out_size) {
    const float* h_in = (const float*)d_in[0];
    const float* W    = (const float*)d_in[1];
    const float* b    = (const float*)d_in[2];
    // d_in[3]=a_src, d_in[4]=a_tgt: provably unused after reduction
    const int* edge_index = (const int*)d_in[5];

    int HF   = in_sizes[2];               // H * F_OUT
    int F_IN = in_sizes[1] / HF;
    int n    = in_sizes[0] / F_IN;
    int E    = in_sizes[5] / 2;
    const int* src = edge_index;          // row 0 of [2, E]

    float* out = (float*)d_out;

    if (F_IN == 128 && HF == 32 && n <= 102400) {
        int mapBytes = (n + 127) & ~127;              // >= nWords*32, 16B aligned
        int smemBytes = mapBytes > 16512 ? mapBytes : 16512;

        static int sm_count = 0;                      // device attr, constant
        if (sm_count == 0) {
            cudaDeviceGetAttribute(&sm_count, cudaDevAttrMultiProcessorCount, 0);
            cudaFuncSetAttribute(fused_kernel,
                                 cudaFuncAttributeMaxDynamicSharedMemorySize,
                                 104000);
        }
        int grid = 2 * sm_count;                      // exactly 2 CTAs/SM, 1 wave

        fused_kernel<<<grid, 256, smemBytes>>>(h_in, W, b, out, n, src, E, mapBytes);
        maskfix_bits_kernel<<<(n + 255) / 256, 256>>>(out, n, HF);
    } else {
        generic_scatter_kernel<<<1024, 256>>>(src, E);
        long long total = (long long)n * HF;
        generic_gemm_kernel<<<(int)((total + 255) / 256), 256>>>(
            h_in, W, b, out, n, F_IN, HF);
        generic_maskfix_kernel<<<(n + 255) / 256, 256>>>(out, n, HF);
    }
    (void)n_in; (void)out_size;
}